// round 5
// baseline (speedup 1.0000x reference)
#include <cuda_runtime.h>
#include <cuda_bf16.h>
#include <cstdint>

#define B_  4
#define S_  2048
#define D_  1024
#define H_  16
#define HD_ 64

// ---------------------------------------------------------------------------
// Static scratch (bf16 hi/lo split form everywhere)
// ---------------------------------------------------------------------------
__device__ __nv_bfloat16 g_xh[3][B_ * S_ * D_], g_xl[3][B_ * S_ * D_];   // split inputs (0=q,1=k,2=v)
__device__ __nv_bfloat16 g_wh[3][H_ * D_ * HD_], g_wl[3][H_ * D_ * HD_]; // split Wq/Wk/Wv
__device__ __nv_bfloat16 g_woh[D_ * D_], g_wol[D_ * D_];                 // split Wo
__device__ __nv_bfloat16 g_qh[B_*H_*S_*HD_], g_ql[B_*H_*S_*HD_];         // [bh][S][64]
__device__ __nv_bfloat16 g_kh[B_*H_*S_*HD_], g_kl[B_*H_*S_*HD_];
__device__ __nv_bfloat16 g_vh[B_*H_*S_*HD_], g_vl[B_*H_*S_*HD_];
__device__ __nv_bfloat16 g_zh[B_ * S_ * D_], g_zl[B_ * S_ * D_];         // [b][s][1024]
__device__ unsigned     g_mpk[B_ * S_ * (S_ / 32)];                      // packed mask bits

// ---------------------------------------------------------------------------
// Helpers
// ---------------------------------------------------------------------------
__device__ __forceinline__ uint32_t pack2(float x, float y) {
    __nv_bfloat162 t = __floats2bfloat162_rn(x, y);
    return *reinterpret_cast<uint32_t*>(&t);
}
__device__ __forceinline__ void split_pack(float x, float y, uint32_t& hi, uint32_t& lo) {
    float hx = __bfloat162float(__float2bfloat16(x));
    float hy = __bfloat162float(__float2bfloat16(y));
    hi = pack2(hx, hy);
    lo = pack2(x - hx, y - hy);
}
__device__ __forceinline__ float ex2(float x) {
    float y; asm("ex2.approx.f32 %0, %1;" : "=f"(y) : "f"(x)); return y;
}
__device__ __forceinline__ uint32_t smem_u32(const void* p) {
    return (uint32_t)__cvta_generic_to_shared(p);
}
__device__ __forceinline__ void ldsm4(uint32_t r[4], uint32_t a) {
    asm volatile("ldmatrix.sync.aligned.m8n8.x4.shared.b16 {%0,%1,%2,%3}, [%4];"
                 : "=r"(r[0]), "=r"(r[1]), "=r"(r[2]), "=r"(r[3]) : "r"(a));
}
__device__ __forceinline__ void ldsm4t(uint32_t r[4], uint32_t a) {
    asm volatile("ldmatrix.sync.aligned.m8n8.x4.trans.shared.b16 {%0,%1,%2,%3}, [%4];"
                 : "=r"(r[0]), "=r"(r[1]), "=r"(r[2]), "=r"(r[3]) : "r"(a));
}
__device__ __forceinline__ void mma_bf16(float c[4], const uint32_t a[4], const uint32_t b[2]) {
    asm volatile(
        "mma.sync.aligned.m16n8k16.row.col.f32.bf16.bf16.f32 "
        "{%0,%1,%2,%3}, {%4,%5,%6,%7}, {%8,%9}, {%0,%1,%2,%3};\n"
        : "+f"(c[0]), "+f"(c[1]), "+f"(c[2]), "+f"(c[3])
        : "r"(a[0]), "r"(a[1]), "r"(a[2]), "r"(a[3]), "r"(b[0]), "r"(b[1]));
}

// ---------------------------------------------------------------------------
// Split kernel: fp32 -> bf16 hi/lo
// ---------------------------------------------------------------------------
__global__ void split_kernel(const float* __restrict__ in, int dst, int n4)
{
    int i = blockIdx.x * 256 + threadIdx.x;
    if (i >= n4) return;
    __nv_bfloat16 *hi, *lo;
    if (dst < 3)      { hi = g_xh[dst];     lo = g_xl[dst]; }
    else if (dst < 6) { hi = g_wh[dst - 3]; lo = g_wl[dst - 3]; }
    else              { hi = g_woh;         lo = g_wol; }
    float4 v = ((const float4*)in)[i];
    uint32_t h0, l0, h1, l1;
    split_pack(v.x, v.y, h0, l0);
    split_pack(v.z, v.w, h1, l1);
    ((uint2*)hi)[i] = make_uint2(h0, h1);
    ((uint2*)lo)[i] = make_uint2(l0, l1);
}

__global__ void pack_mask_kernel(const int* __restrict__ mask)
{
    int i = blockIdx.x * 256 + threadIdx.x;
    if (i >= B_ * S_ * (S_ / 32)) return;
    const int4* mp = (const int4*)(mask + (long)i * 32);
    unsigned w = 0;
#pragma unroll
    for (int j = 0; j < 8; j++) {
        int4 m = mp[j];
        w |= (unsigned)(m.x != 0) << (j * 4 + 0);
        w |= (unsigned)(m.y != 0) << (j * 4 + 1);
        w |= (unsigned)(m.z != 0) << (j * 4 + 2);
        w |= (unsigned)(m.w != 0) << (j * 4 + 3);
    }
    g_mpk[i] = w;
}

// ---------------------------------------------------------------------------
// Unified GEMM body: 128(m) x 128(n) x K, chunk 32, 256 threads = 8 warps
// (4m x 2n), warp tile 32x64. B addressing supports head-strided layout:
// addr(k, col) = Bg + (col>>6)*bHS + k*ldb + (col&63)   [col in bf16 units]
//   qkv:      bHS = D*HD (per-head W), ldb = 64
//   outproj:  bHS = 64,               ldb = D  (degenerates to k*D + col)
// ---------------------------------------------------------------------------
template<bool SPLIT_OUT>
__device__ __forceinline__ void gemm_body(
    const __nv_bfloat16* __restrict__ Agh, const __nv_bfloat16* __restrict__ Agl,
    int lda, int kdim,
    const __nv_bfloat16* __restrict__ Bgh, const __nv_bfloat16* __restrict__ Bgl,
    long bHS, int ldb,
    const float* __restrict__ bias,
    float* __restrict__ outF, int ldoF,
    __nv_bfloat16* __restrict__ outH, __nv_bfloat16* __restrict__ outL, long outHS)
{
    __shared__ uint32_t sAh[128 * 20], sAl[128 * 20];   // pitch 80B (32 bf16 + 8 pad)
    __shared__ uint32_t sBh[32 * 68],  sBl[32 * 68];    // pitch 272B (128 bf16 + 8 pad)

    const int t = threadIdx.x, lane = t & 31, warp = t >> 5;
    const int wm = warp >> 1, wn = warp & 1;
    const int lr = lane >> 2, lc = lane & 3;
    const int g = lane >> 3, lr8 = lane & 7;

    const int ar = t >> 2, asc = t & 3;          // A staging: rows ar, ar+64
    const int brow = t >> 4, bc16 = t & 15;      // B staging: rows brow, brow+16

    float c[2][8][4];
#pragma unroll
    for (int i = 0; i < 2; i++)
#pragma unroll
        for (int j = 0; j < 8; j++)
#pragma unroll
            for (int k = 0; k < 4; k++) c[i][j][k] = 0.f;

    const uint32_t aBH = smem_u32(sAh) + (wm * 32 + lr8 + ((g & 1) << 3)) * 80 + ((g >> 1) << 4);
    const uint32_t aBL = aBH + (smem_u32(sAl) - smem_u32(sAh));
    const uint32_t bBH = smem_u32(sBh) + (lr8 + ((g & 1) << 3)) * 272 + wn * 128 + ((g >> 1) << 4);
    const uint32_t bBL = bBH + (smem_u32(sBl) - smem_u32(sBh));

    const __nv_bfloat16* bAddrH = Bgh + (bc16 >> 3) * bHS + (bc16 & 7) * 8;
    const __nv_bfloat16* bAddrL = Bgl + (bc16 >> 3) * bHS + (bc16 & 7) * 8;

    uint4 rah0, rah1, ral0, ral1, rbh0, rbh1, rbl0, rbl1;
#define GEMM_LOAD(k0) do { \
        rah0 = *(const uint4*)(Agh + (long)ar        * lda + (k0) + asc * 8); \
        rah1 = *(const uint4*)(Agh + (long)(ar + 64) * lda + (k0) + asc * 8); \
        ral0 = *(const uint4*)(Agl + (long)ar        * lda + (k0) + asc * 8); \
        ral1 = *(const uint4*)(Agl + (long)(ar + 64) * lda + (k0) + asc * 8); \
        rbh0 = *(const uint4*)(bAddrH + (long)((k0) + brow)      * ldb); \
        rbh1 = *(const uint4*)(bAddrH + (long)((k0) + brow + 16) * ldb); \
        rbl0 = *(const uint4*)(bAddrL + (long)((k0) + brow)      * ldb); \
        rbl1 = *(const uint4*)(bAddrL + (long)((k0) + brow + 16) * ldb); \
    } while (0)

    GEMM_LOAD(0);
    const int nchunks = kdim / 32;
    for (int ch = 0; ch < nchunks; ch++) {
        __syncthreads();
        ((uint4*)sAh)[ar * 5 + asc]           = rah0;
        ((uint4*)sAh)[(ar + 64) * 5 + asc]    = rah1;
        ((uint4*)sAl)[ar * 5 + asc]           = ral0;
        ((uint4*)sAl)[(ar + 64) * 5 + asc]    = ral1;
        ((uint4*)sBh)[brow * 17 + bc16]        = rbh0;
        ((uint4*)sBh)[(brow + 16) * 17 + bc16] = rbh1;
        ((uint4*)sBl)[brow * 17 + bc16]        = rbl0;
        ((uint4*)sBl)[(brow + 16) * 17 + bc16] = rbl1;
        __syncthreads();
        if (ch + 1 < nchunks) GEMM_LOAD((ch + 1) * 32);

#pragma unroll
        for (int ks = 0; ks < 2; ks++) {
            uint32_t ah[2][4], al[2][4];
#pragma unroll
            for (int ma = 0; ma < 2; ma++) {
                ldsm4(ah[ma], aBH + ma * 1280 + ks * 32);
                ldsm4(al[ma], aBL + ma * 1280 + ks * 32);
            }
#pragma unroll
            for (int np = 0; np < 4; np++) {
                uint32_t bh4[4], bl4[4];
                // ks advances 16 k-rows: 16 * 272B = 4352B  (R4 bug was 2176)
                ldsm4t(bh4, bBH + ks * 4352 + np * 32);
                ldsm4t(bl4, bBL + ks * 4352 + np * 32);
#pragma unroll
                for (int ma = 0; ma < 2; ma++) {
                    mma_bf16(c[ma][np * 2],     ah[ma], bh4);
                    mma_bf16(c[ma][np * 2],     ah[ma], bl4);
                    mma_bf16(c[ma][np * 2],     al[ma], bh4);
                    mma_bf16(c[ma][np * 2 + 1], ah[ma], bh4 + 2);
                    mma_bf16(c[ma][np * 2 + 1], ah[ma], bl4 + 2);
                    mma_bf16(c[ma][np * 2 + 1], al[ma], bh4 + 2);
                }
            }
        }
    }
#undef GEMM_LOAD

    // epilogue
#pragma unroll
    for (int ma = 0; ma < 2; ma++) {
#pragma unroll
        for (int na = 0; na < 8; na++) {
            int r   = wm * 32 + ma * 16 + lr;
            int col = wn * 64 + na * 8 + lc * 2;
            float b0 = bias[col], b1 = bias[col + 1];
            float v00 = c[ma][na][0] + b0, v01 = c[ma][na][1] + b1;
            float v10 = c[ma][na][2] + b0, v11 = c[ma][na][3] + b1;
            if (SPLIT_OUT) {
                int head = col >> 6, e = col & 63;
                __nv_bfloat16* ph = outH + head * outHS + (long)r * 64 + e;
                __nv_bfloat16* pl = outL + head * outHS + (long)r * 64 + e;
                uint32_t hh, ll;
                split_pack(v00, v01, hh, ll);
                *(uint32_t*)ph = hh; *(uint32_t*)pl = ll;
                split_pack(v10, v11, hh, ll);
                *(uint32_t*)(ph + 8 * 64) = hh; *(uint32_t*)(pl + 8 * 64) = ll;
            } else {
                *(float2*)(outF + (long)r * ldoF + col)       = make_float2(v00, v01);
                *(float2*)(outF + (long)(r + 8) * ldoF + col) = make_float2(v10, v11);
            }
        }
    }
}

// ---------------------------------------------------------------------------
// QKV projection: grid (H/2 = 8, B*S/128 = 64, 3). N-tile covers 2 heads.
// ---------------------------------------------------------------------------
__global__ __launch_bounds__(256) void qkv_gemm(
    const float* __restrict__ bq, const float* __restrict__ bk, const float* __restrict__ bv)
{
    const int which = blockIdx.z;
    const int h0 = blockIdx.x * 2;
    const int b  = blockIdx.y >> 4;
    const int s0 = (blockIdx.y & 15) * 128;

    const __nv_bfloat16* Agh = g_xh[which] + ((long)b * S_ + s0) * D_;
    const __nv_bfloat16* Agl = g_xl[which] + ((long)b * S_ + s0) * D_;
    const __nv_bfloat16* Bgh = g_wh[which] + (long)h0 * D_ * HD_;
    const __nv_bfloat16* Bgl = g_wl[which] + (long)h0 * D_ * HD_;
    const float* bias = ((which == 0) ? bq : (which == 1) ? bk : bv) + h0 * HD_;

    long obase = ((long)(b * H_ + h0) * S_ + s0) * HD_;
    __nv_bfloat16* oh = ((which == 0) ? g_qh : (which == 1) ? g_kh : g_vh) + obase;
    __nv_bfloat16* ol = ((which == 0) ? g_ql : (which == 1) ? g_kl : g_vl) + obase;

    gemm_body<true>(Agh, Agl, D_, D_, Bgh, Bgl, (long)D_ * HD_, HD_,
                    bias, nullptr, 0, oh, ol, (long)S_ * HD_);
}

// ---------------------------------------------------------------------------
// Output projection: grid (D/128 = 8, B*S/128 = 64)
// ---------------------------------------------------------------------------
__global__ __launch_bounds__(256) void outproj_gemm(
    const float* __restrict__ bo, float* __restrict__ out)
{
    const int n0 = blockIdx.x * 128;
    const long m0 = (long)blockIdx.y * 128;
    gemm_body<false>(g_zh + m0 * D_, g_zl + m0 * D_, D_, D_,
                     g_woh + n0, g_wol + n0, 64, D_,
                     bo + n0, out + m0 * D_ + n0, D_, nullptr, nullptr, 0);
}

// ---------------------------------------------------------------------------
// Flash attention: 128 q-rows/block, 256 thr = 8 warps (16 q-rows each),
// 64-key tiles. Mask->0-before-softmax semantics, base-2, fixed max 0.
// grid (S/128 = 16, B*H = 64)
// ---------------------------------------------------------------------------
__global__ __launch_bounds__(256) void attn_kernel()
{
    __shared__ uint32_t sm4[4][64 * 36];   // 0=Kh 1=Kl 2=Vh 3=Vl (Q staged across all 4)

    const int t = threadIdx.x, lane = t & 31, w = t >> 5;
    const int lr = lane >> 2, lc = lane & 3;
    const int g = lane >> 3, lr8 = lane & 7;
    const int bh = blockIdx.y, b = bh >> 4, h = bh & 15;
    const int q0 = blockIdx.x * 128;

    const __nv_bfloat16* qgh = g_qh + ((long)bh * S_ + q0) * HD_;
    const __nv_bfloat16* qgl = g_ql + ((long)bh * S_ + q0) * HD_;
    const __nv_bfloat16* khb = g_kh + (long)bh * S_ * HD_;
    const __nv_bfloat16* klb = g_kl + (long)bh * S_ * HD_;
    const __nv_bfloat16* vhb = g_vh + (long)bh * S_ * HD_;
    const __nv_bfloat16* vlb = g_vl + (long)bh * S_ * HD_;
    const float SC = 0.125f * 1.44269504088896340736f;

    // ---- stage Q tile [128][64] hi/lo across the 4 buffers ----
#pragma unroll
    for (int i = 0; i < 4; i++) {
        int s = t + i * 256, row = s >> 3, sc = s & 7;
        int bufh = (row < 64) ? 0 : 2;
        ((uint4*)sm4[bufh])[(row & 63) * 9 + sc]     = *(const uint4*)(qgh + (long)row * HD_ + sc * 8);
        ((uint4*)sm4[bufh + 1])[(row & 63) * 9 + sc] = *(const uint4*)(qgl + (long)row * HD_ + sc * 8);
    }
    __syncthreads();
    uint32_t qh[4][4], ql[4][4];
    {
        const uint32_t* bufH = sm4[(w < 4) ? 0 : 2];
        const uint32_t* bufL = sm4[(w < 4) ? 1 : 3];
        uint32_t qBH = smem_u32(bufH) + ((w & 3) * 16 + lr8 + ((g & 1) << 3)) * 144 + ((g >> 1) << 4);
        uint32_t qBL = smem_u32(bufL) + ((w & 3) * 16 + lr8 + ((g & 1) << 3)) * 144 + ((g >> 1) << 4);
#pragma unroll
        for (int ks = 0; ks < 4; ks++) {
            ldsm4(qh[ks], qBH + ks * 32);
            ldsm4(ql[ks], qBL + ks * 32);
        }
    }
    __syncthreads();

    float o[8][4];
#pragma unroll
    for (int i = 0; i < 8; i++)
#pragma unroll
        for (int j = 0; j < 4; j++) o[i][j] = 0.f;
    float lacc[2] = {0.f, 0.f};

    const uint32_t kBH = smem_u32(sm4[0]) + (lr8 + ((g >= 2) << 3)) * 144 + ((g & 1) << 4);
    const uint32_t kBL = smem_u32(sm4[1]) + (lr8 + ((g >= 2) << 3)) * 144 + ((g & 1) << 4);
    const uint32_t vBH = smem_u32(sm4[2]) + (lr8 + ((g & 1) << 3)) * 144 + ((g >> 1) << 4);
    const uint32_t vBL = smem_u32(sm4[3]) + (lr8 + ((g & 1) << 3)) * 144 + ((g >> 1) << 4);

    uint4 rk[4];
#define KV_LOAD(dst, srcH, srcL, kk0) do { \
        _Pragma("unroll") \
        for (int i = 0; i < 4; i++) { \
            int s = t + (i & 1) * 256, row = s >> 3, sc = s & 7; \
            const __nv_bfloat16* p = ((i < 2) ? (srcH) : (srcL)) + ((long)((kk0) + row)) * HD_ + sc * 8; \
            dst[i] = *(const uint4*)p; \
        } \
    } while (0)

    KV_LOAD(rk, khb, klb, 0);

    for (int kt = 0; kt < S_ / 64; kt++) {
        const int k0 = kt * 64;
        __syncthreads();   // prior QK/PV reads complete
        // ---- STS K tile ----
#pragma unroll
        for (int i = 0; i < 4; i++) {
            int s = t + (i & 1) * 256, row = s >> 3, sc = s & 7;
            ((uint4*)sm4[(i < 2) ? 0 : 1])[row * 9 + sc] = rk[i];
        }
        __syncthreads();

        // ---- prefetch V + mask ----
        uint4 rv[4];
        KV_LOAD(rv, vhb, vlb, k0);
        uint32_t mw[2][2];
#pragma unroll
        for (int i = 0; i < 2; i++) {
            int q = q0 + w * 16 + lr + i * 8;
            const unsigned* mp = g_mpk + ((long)b * S_ + q) * (S_ / 32) + (k0 >> 5);
            mw[i][0] = mp[0]; mw[i][1] = mp[1];
        }

        // ---- S = Q K^T ----
        float s_[8][4];
#pragma unroll
        for (int i = 0; i < 8; i++)
#pragma unroll
            for (int j = 0; j < 4; j++) s_[i][j] = 0.f;
#pragma unroll
        for (int ks = 0; ks < 4; ks++) {
#pragma unroll
            for (int np = 0; np < 4; np++) {
                uint32_t kb[4], kl4[4];
                ldsm4(kb,  kBH + np * 2304 + ks * 32);
                ldsm4(kl4, kBL + np * 2304 + ks * 32);
                mma_bf16(s_[np * 2],     qh[ks], kb);
                mma_bf16(s_[np * 2],     qh[ks], kl4);
                mma_bf16(s_[np * 2],     ql[ks], kb);
                mma_bf16(s_[np * 2 + 1], qh[ks], kb + 2);
                mma_bf16(s_[np * 2 + 1], qh[ks], kl4 + 2);
                mma_bf16(s_[np * 2 + 1], ql[ks], kb + 2);
            }
        }

        // ---- mask + exp2 (fixed max 0) ----
#pragma unroll
        for (int i = 0; i < 2; i++) {
#pragma unroll
            for (int na = 0; na < 8; na++) {
                uint32_t wbits = mw[i][na >> 2];
                int bit = (na & 3) * 8 + lc * 2;
                float v0 = ((wbits >> bit) & 1)       ? s_[na][i * 2] * SC     : 0.f;
                float v1 = ((wbits >> (bit + 1)) & 1) ? s_[na][i * 2 + 1] * SC : 0.f;
                float p0 = ex2(v0), p1 = ex2(v1);
                s_[na][i * 2] = p0; s_[na][i * 2 + 1] = p1;
                lacc[i] += p0 + p1;
            }
        }

        // ---- split P into A-frags ----
        uint32_t pah[4][4], pal[4][4];
#pragma unroll
        for (int ks = 0; ks < 4; ks++) {
            split_pack(s_[2 * ks][0],     s_[2 * ks][1],     pah[ks][0], pal[ks][0]);
            split_pack(s_[2 * ks][2],     s_[2 * ks][3],     pah[ks][1], pal[ks][1]);
            split_pack(s_[2 * ks + 1][0], s_[2 * ks + 1][1], pah[ks][2], pal[ks][2]);
            split_pack(s_[2 * ks + 1][2], s_[2 * ks + 1][3], pah[ks][3], pal[ks][3]);
        }

        // ---- STS V tile ----
#pragma unroll
        for (int i = 0; i < 4; i++) {
            int s = t + (i & 1) * 256, row = s >> 3, sc = s & 7;
            ((uint4*)sm4[(i < 2) ? 2 : 3])[row * 9 + sc] = rv[i];
        }
        __syncthreads();

        // ---- prefetch next K ----
        if (kt + 1 < S_ / 64) KV_LOAD(rk, khb, klb, k0 + 64);

        // ---- O += P V ----
#pragma unroll
        for (int ks = 0; ks < 4; ks++) {
#pragma unroll
            for (int np = 0; np < 4; np++) {
                uint32_t vb[4], vl4[4];
                ldsm4t(vb,  vBH + ks * 2304 + np * 32);
                ldsm4t(vl4, vBL + ks * 2304 + np * 32);
                mma_bf16(o[np * 2],     pah[ks], vb);
                mma_bf16(o[np * 2],     pah[ks], vl4);
                mma_bf16(o[np * 2],     pal[ks], vb);
                mma_bf16(o[np * 2 + 1], pah[ks], vb + 2);
                mma_bf16(o[np * 2 + 1], pah[ks], vl4 + 2);
                mma_bf16(o[np * 2 + 1], pal[ks], vb + 2);
            }
        }
    }
#undef KV_LOAD

    // ---- epilogue: z split to bf16 hi/lo ----
#pragma unroll
    for (int i = 0; i < 2; i++) {
        lacc[i] += __shfl_xor_sync(0xffffffffu, lacc[i], 1);
        lacc[i] += __shfl_xor_sync(0xffffffffu, lacc[i], 2);
        float inv = 1.f / lacc[i];
        int q = q0 + w * 16 + lr + i * 8;
        __nv_bfloat16* zh = g_zh + ((long)b * S_ + q) * D_ + h * HD_;
        __nv_bfloat16* zl = g_zl + ((long)b * S_ + q) * D_ + h * HD_;
#pragma unroll
        for (int na = 0; na < 8; na++) {
            uint32_t hh, ll;
            split_pack(o[na][i * 2] * inv, o[na][i * 2 + 1] * inv, hh, ll);
            *(uint32_t*)(zh + na * 8 + lc * 2) = hh;
            *(uint32_t*)(zl + na * 8 + lc * 2) = ll;
        }
    }
}

// ---------------------------------------------------------------------------
extern "C" void kernel_launch(void* const* d_in, const int* in_sizes, int n_in,
                              void* d_out, int out_size)
{
    const float* xv   = (const float*)d_in[0];
    const float* xk   = (const float*)d_in[1];
    const float* xq   = (const float*)d_in[2];
    const int*   mask = (const int*)  d_in[3];
    const float* Wq   = (const float*)d_in[4];
    const float* bq   = (const float*)d_in[5];
    const float* Wk   = (const float*)d_in[6];
    const float* bk   = (const float*)d_in[7];
    const float* Wv   = (const float*)d_in[8];
    const float* bv   = (const float*)d_in[9];
    const float* Wo   = (const float*)d_in[10];
    const float* bo   = (const float*)d_in[11];
    float* out = (float*)d_out;

    const int nx4 = B_ * S_ * D_ / 4;
    const int nw4 = H_ * D_ * HD_ / 4;

    split_kernel<<<(nx4 + 255) / 256, 256>>>(xq, 0, nx4);
    split_kernel<<<(nx4 + 255) / 256, 256>>>(xk, 1, nx4);
    split_kernel<<<(nx4 + 255) / 256, 256>>>(xv, 2, nx4);
    split_kernel<<<(nw4 + 255) / 256, 256>>>(Wq, 3, nw4);
    split_kernel<<<(nw4 + 255) / 256, 256>>>(Wk, 4, nw4);
    split_kernel<<<(nw4 + 255) / 256, 256>>>(Wv, 5, nw4);
    split_kernel<<<(nw4 + 255) / 256, 256>>>(Wo, 6, nw4);
    pack_mask_kernel<<<(B_ * S_ * (S_ / 32) + 255) / 256, 256>>>(mask);

    qkv_gemm<<<dim3(H_ / 2, (B_ * S_) / 128, 3), 256>>>(bq, bk, bv);
    attn_kernel<<<dim3(S_ / 128, B_ * H_), 256>>>();
    outproj_gemm<<<dim3(D_ / 128, (B_ * S_) / 128), 256>>>(bo, out);
}

// round 7
// speedup vs baseline: 1.1422x; 1.1422x over previous
#include <cuda_runtime.h>
#include <cuda_bf16.h>
#include <cstdint>

#define B_  4
#define S_  2048
#define D_  1024
#define H_  16
#define HD_ 64

// ---------------------------------------------------------------------------
// Static scratch (bf16 hi/lo split form everywhere), 16B-aligned for cp.async
// ---------------------------------------------------------------------------
__device__ __align__(16) __nv_bfloat16 g_xh[3][B_ * S_ * D_], g_xl[3][B_ * S_ * D_];
__device__ __align__(16) __nv_bfloat16 g_wh[3][H_ * D_ * HD_], g_wl[3][H_ * D_ * HD_];
__device__ __align__(16) __nv_bfloat16 g_woh[D_ * D_], g_wol[D_ * D_];
__device__ __align__(16) __nv_bfloat16 g_qh[B_*H_*S_*HD_], g_ql[B_*H_*S_*HD_];
__device__ __align__(16) __nv_bfloat16 g_kh[B_*H_*S_*HD_], g_kl[B_*H_*S_*HD_];
__device__ __align__(16) __nv_bfloat16 g_vh[B_*H_*S_*HD_], g_vl[B_*H_*S_*HD_];
__device__ __align__(16) __nv_bfloat16 g_zh[B_ * S_ * D_], g_zl[B_ * S_ * D_];
__device__ unsigned g_mpk[B_ * S_ * (S_ / 32)];

// ---------------------------------------------------------------------------
// Helpers
// ---------------------------------------------------------------------------
__device__ __forceinline__ uint32_t pack2(float x, float y) {
    __nv_bfloat162 t = __floats2bfloat162_rn(x, y);
    return *reinterpret_cast<uint32_t*>(&t);
}
__device__ __forceinline__ void split_pack(float x, float y, uint32_t& hi, uint32_t& lo) {
    float hx = __bfloat162float(__float2bfloat16(x));
    float hy = __bfloat162float(__float2bfloat16(y));
    hi = pack2(hx, hy);
    lo = pack2(x - hx, y - hy);
}
__device__ __forceinline__ float ex2(float x) {
    float y; asm("ex2.approx.f32 %0, %1;" : "=f"(y) : "f"(x)); return y;
}
__device__ __forceinline__ uint32_t smem_u32(const void* p) {
    return (uint32_t)__cvta_generic_to_shared(p);
}
__device__ __forceinline__ void ldsm4(uint32_t r[4], uint32_t a) {
    asm volatile("ldmatrix.sync.aligned.m8n8.x4.shared.b16 {%0,%1,%2,%3}, [%4];"
                 : "=r"(r[0]), "=r"(r[1]), "=r"(r[2]), "=r"(r[3]) : "r"(a));
}
__device__ __forceinline__ void ldsm4t(uint32_t r[4], uint32_t a) {
    asm volatile("ldmatrix.sync.aligned.m8n8.x4.trans.shared.b16 {%0,%1,%2,%3}, [%4];"
                 : "=r"(r[0]), "=r"(r[1]), "=r"(r[2]), "=r"(r[3]) : "r"(a));
}
__device__ __forceinline__ void mma_bf16(float c[4], const uint32_t a[4], const uint32_t b[2]) {
    asm volatile(
        "mma.sync.aligned.m16n8k16.row.col.f32.bf16.bf16.f32 "
        "{%0,%1,%2,%3}, {%4,%5,%6,%7}, {%8,%9}, {%0,%1,%2,%3};\n"
        : "+f"(c[0]), "+f"(c[1]), "+f"(c[2]), "+f"(c[3])
        : "r"(a[0]), "r"(a[1]), "r"(a[2]), "r"(a[3]), "r"(b[0]), "r"(b[1]));
}
__device__ __forceinline__ void cpa16(uint32_t saddr, const void* g) {
    asm volatile("cp.async.cg.shared.global [%0], [%1], 16;" :: "r"(saddr), "l"(g) : "memory");
}
__device__ __forceinline__ void cpa_commit() { asm volatile("cp.async.commit_group;" ::: "memory"); }
__device__ __forceinline__ void cpa_wait0()  { asm volatile("cp.async.wait_group 0;" ::: "memory"); }
__device__ __forceinline__ void cpa_wait1()  { asm volatile("cp.async.wait_group 1;" ::: "memory"); }

// ---------------------------------------------------------------------------
// Split kernels (fp32 -> bf16 hi/lo)
// ---------------------------------------------------------------------------
__global__ void split_kernel(const float* __restrict__ in, int dst, int n4)
{
    int i = blockIdx.x * 256 + threadIdx.x;
    if (i >= n4) return;
    __nv_bfloat16 *hi, *lo;
    if (dst < 3)      { hi = g_xh[dst];     lo = g_xl[dst]; }
    else if (dst < 6) { hi = g_wh[dst - 3]; lo = g_wl[dst - 3]; }
    else              { hi = g_woh;         lo = g_wol; }
    float4 v = ((const float4*)in)[i];
    uint32_t h0, l0, h1, l1;
    split_pack(v.x, v.y, h0, l0);
    split_pack(v.z, v.w, h1, l1);
    ((uint2*)hi)[i] = make_uint2(h0, h1);
    ((uint2*)lo)[i] = make_uint2(l0, l1);
}

__global__ void pack_mask_kernel(const int* __restrict__ mask)
{
    int i = blockIdx.x * 256 + threadIdx.x;
    if (i >= B_ * S_ * (S_ / 32)) return;
    const int4* mp = (const int4*)(mask + (long)i * 32);
    unsigned w = 0;
#pragma unroll
    for (int j = 0; j < 8; j++) {
        int4 m = mp[j];
        w |= (unsigned)(m.x != 0) << (j * 4 + 0);
        w |= (unsigned)(m.y != 0) << (j * 4 + 1);
        w |= (unsigned)(m.z != 0) << (j * 4 + 2);
        w |= (unsigned)(m.w != 0) << (j * 4 + 3);
    }
    g_mpk[i] = w;
}

// ---------------------------------------------------------------------------
// GEMM: 128(m) x 64(n) x kdim, k-chunks of 64, 2-stage cp.async pipeline.
// 256 threads = 8 warps (4m x 2n), warp tile 32x32. Rows 144B pitch.
// Stage layout (55296 B): Ah[128x144] Al[128x144] Bh[64x144] Bl[64x144]
// ---------------------------------------------------------------------------
#define G_STG   55296
#define G_AL    18432
#define G_BH    36864
#define G_BL    46080
#define GEMM_DSM (2 * G_STG)

template<bool SPLIT_OUT>
__device__ __forceinline__ void gemm_body(
    const __nv_bfloat16* __restrict__ Agh, const __nv_bfloat16* __restrict__ Agl,
    int lda, int kdim,
    const __nv_bfloat16* __restrict__ Bgh, const __nv_bfloat16* __restrict__ Bgl, int ldb,
    const float* __restrict__ bias,
    float* __restrict__ outF, int ldoF,
    __nv_bfloat16* __restrict__ outH, __nv_bfloat16* __restrict__ outL)
{
    extern __shared__ uint8_t dyn[];
    const uint32_t sb = smem_u32(dyn);

    const int t = threadIdx.x, lane = t & 31, warp = t >> 5;
    const int wm = warp >> 1, wn = warp & 1;
    const int lr = lane >> 2, lc = lane & 3;
    const int g = lane >> 3, lr8 = lane & 7;

    float c[2][4][4];
#pragma unroll
    for (int i = 0; i < 2; i++)
#pragma unroll
        for (int j = 0; j < 4; j++)
#pragma unroll
            for (int k = 0; k < 4; k++) c[i][j][k] = 0.f;

#define G_ISSUE(stg, k0) do { \
        uint32_t base_ = sb + (stg) * G_STG; \
        _Pragma("unroll") \
        for (int j = 0; j < 4; j++) { \
            int idx = t + j * 256, r = idx >> 3, cc = idx & 7; \
            cpa16(base_ + r * 144 + cc * 16,          Agh + (long)r * lda + (k0) + cc * 8); \
            cpa16(base_ + G_AL + r * 144 + cc * 16,   Agl + (long)r * lda + (k0) + cc * 8); \
        } \
        _Pragma("unroll") \
        for (int j = 0; j < 2; j++) { \
            int idx = t + j * 256, r = idx >> 3, cc = idx & 7; \
            cpa16(base_ + G_BH + r * 144 + cc * 16,   Bgh + (long)((k0) + r) * ldb + cc * 8); \
            cpa16(base_ + G_BL + r * 144 + cc * 16,   Bgl + (long)((k0) + r) * ldb + cc * 8); \
        } \
        cpa_commit(); \
    } while (0)

    G_ISSUE(0, 0);
    const int nchunks = kdim / 64;
    for (int ch = 0; ch < nchunks; ch++) {
        const int s = ch & 1;
        __syncthreads();                       // prior compute done before overwrite
        if (ch + 1 < nchunks) { G_ISSUE(1 - s, (ch + 1) * 64); cpa_wait1(); }
        else                  { cpa_wait0(); }
        __syncthreads();

        const uint32_t stb = sb + s * G_STG;
        const uint32_t aBH = stb + (wm * 32 + lr8 + ((g & 1) << 3)) * 144 + ((g >> 1) << 4);
        const uint32_t aBL = aBH + G_AL;
        const uint32_t bBH = stb + G_BH + (lr8 + ((g & 1) << 3)) * 144 + wn * 64 + ((g >> 1) << 4);
        const uint32_t bBL = bBH + (G_BL - G_BH);

#pragma unroll
        for (int ks = 0; ks < 4; ks++) {
            uint32_t ah[2][4], al[2][4];
#pragma unroll
            for (int ma = 0; ma < 2; ma++) {
                ldsm4(ah[ma], aBH + ma * 2304 + ks * 32);
                ldsm4(al[ma], aBL + ma * 2304 + ks * 32);
            }
#pragma unroll
            for (int np = 0; np < 2; np++) {
                uint32_t bh4[4], bl4[4];
                ldsm4t(bh4, bBH + ks * 2304 + np * 32);
                ldsm4t(bl4, bBL + ks * 2304 + np * 32);
#pragma unroll
                for (int ma = 0; ma < 2; ma++) {
                    mma_bf16(c[ma][np * 2],     ah[ma], bh4);
                    mma_bf16(c[ma][np * 2],     ah[ma], bl4);
                    mma_bf16(c[ma][np * 2],     al[ma], bh4);
                    mma_bf16(c[ma][np * 2 + 1], ah[ma], bh4 + 2);
                    mma_bf16(c[ma][np * 2 + 1], ah[ma], bl4 + 2);
                    mma_bf16(c[ma][np * 2 + 1], al[ma], bh4 + 2);
                }
            }
        }
    }
#undef G_ISSUE

    // epilogue
#pragma unroll
    for (int ma = 0; ma < 2; ma++) {
#pragma unroll
        for (int na = 0; na < 4; na++) {
            int r   = wm * 32 + ma * 16 + lr;
            int col = wn * 32 + na * 8 + lc * 2;
            float b0 = bias[col], b1 = bias[col + 1];
            float v00 = c[ma][na][0] + b0, v01 = c[ma][na][1] + b1;
            float v10 = c[ma][na][2] + b0, v11 = c[ma][na][3] + b1;
            if (SPLIT_OUT) {
                __nv_bfloat16* ph = outH + (long)r * HD_ + col;
                __nv_bfloat16* pl = outL + (long)r * HD_ + col;
                uint32_t hh, ll;
                split_pack(v00, v01, hh, ll);
                *(uint32_t*)ph = hh; *(uint32_t*)pl = ll;
                split_pack(v10, v11, hh, ll);
                *(uint32_t*)(ph + 8 * HD_) = hh; *(uint32_t*)(pl + 8 * HD_) = ll;
            } else {
                *(float2*)(outF + (long)r * ldoF + col)       = make_float2(v00, v01);
                *(float2*)(outF + (long)(r + 8) * ldoF + col) = make_float2(v10, v11);
            }
        }
    }
}

__global__ __launch_bounds__(256) void qkv_gemm(
    const float* __restrict__ bq, const float* __restrict__ bk, const float* __restrict__ bv)
{
    const int which = blockIdx.z;
    const int bh = blockIdx.y, b = bh >> 4, h = bh & 15;
    const int s0 = blockIdx.x * 128;

    const __nv_bfloat16* Agh = g_xh[which] + ((long)b * S_ + s0) * D_;
    const __nv_bfloat16* Agl = g_xl[which] + ((long)b * S_ + s0) * D_;
    const __nv_bfloat16* Bgh = g_wh[which] + (long)h * D_ * HD_;
    const __nv_bfloat16* Bgl = g_wl[which] + (long)h * D_ * HD_;
    const float* bias = ((which == 0) ? bq : (which == 1) ? bk : bv) + h * HD_;

    long ob = ((long)bh * S_ + s0) * HD_;
    __nv_bfloat16* oh = ((which == 0) ? g_qh : (which == 1) ? g_kh : g_vh) + ob;
    __nv_bfloat16* ol = ((which == 0) ? g_ql : (which == 1) ? g_kl : g_vl) + ob;

    gemm_body<true>(Agh, Agl, D_, D_, Bgh, Bgl, HD_, bias, nullptr, 0, oh, ol);
}

__global__ __launch_bounds__(256) void outproj_gemm(
    const float* __restrict__ bo, float* __restrict__ out)
{
    const int n0 = blockIdx.x * 64;
    const long m0 = (long)blockIdx.y * 128;
    gemm_body<false>(g_zh + m0 * D_, g_zl + m0 * D_, D_, D_,
                     g_woh + n0, g_wol + n0, D_,
                     bo + n0, out + m0 * D_ + n0, D_, nullptr, nullptr);
}

// ---------------------------------------------------------------------------
// Flash attention: 64 q-rows/block, 128 thr = 4 warps, 64-key tiles,
// 2-stage cp.async pipeline (K+V in one group -> no syncs inside a tile).
// Stage layout (36864 B): Kh[64x144] Kl Vh Vl. Q pre-staged in stage 1.
// ---------------------------------------------------------------------------
#define A_STG  36864
#define A_KL   9216
#define A_VH   18432
#define A_VL   27648
#define ATT_DSM (2 * A_STG)

__global__ __launch_bounds__(128) void attn_kernel()
{
    extern __shared__ uint8_t dyn[];
    const uint32_t sb = smem_u32(dyn);

    const int t = threadIdx.x, lane = t & 31, w = t >> 5;
    const int lr = lane >> 2, lc = lane & 3;
    const int g = lane >> 3, lr8 = lane & 7;
    const int bh = blockIdx.y, b = bh >> 4, h = bh & 15;
    const int q0 = blockIdx.x * 64;

    const __nv_bfloat16* qgh = g_qh + ((long)bh * S_ + q0) * HD_;
    const __nv_bfloat16* qgl = g_ql + ((long)bh * S_ + q0) * HD_;
    const __nv_bfloat16* khb = g_kh + (long)bh * S_ * HD_;
    const __nv_bfloat16* klb = g_kl + (long)bh * S_ * HD_;
    const __nv_bfloat16* vhb = g_vh + (long)bh * S_ * HD_;
    const __nv_bfloat16* vlb = g_vl + (long)bh * S_ * HD_;
    const float SC = 0.125f * 1.44269504088896340736f;

    // ---- stage Q into stage-1 K area via cp.async, read frags ----
#pragma unroll
    for (int j = 0; j < 4; j++) {
        int idx = t + j * 128, r = idx >> 3, cc = idx & 7;
        cpa16(sb + A_STG + r * 144 + cc * 16,        qgh + (long)r * HD_ + cc * 8);
        cpa16(sb + A_STG + A_KL + r * 144 + cc * 16, qgl + (long)r * HD_ + cc * 8);
    }
    cpa_commit();
    cpa_wait0();
    __syncthreads();

    uint32_t qh[4][4], ql[4][4];
    {
        uint32_t qBH = sb + A_STG + (w * 16 + lr8 + ((g & 1) << 3)) * 144 + ((g >> 1) << 4);
        uint32_t qBL = qBH + A_KL;
#pragma unroll
        for (int ks = 0; ks < 4; ks++) {
            ldsm4(qh[ks], qBH + ks * 32);
            ldsm4(ql[ks], qBL + ks * 32);
        }
    }
    __syncthreads();   // all warps done with stage 1 before tile-1 loads hit it

#define KV_ISSUE(stg, k0) do { \
        uint32_t base_ = sb + (stg) * A_STG; \
        _Pragma("unroll") \
        for (int j = 0; j < 4; j++) { \
            int idx = t + j * 128, r = idx >> 3, cc = idx & 7; \
            long go = (long)((k0) + r) * HD_ + cc * 8; \
            cpa16(base_ + r * 144 + cc * 16,        khb + go); \
            cpa16(base_ + A_KL + r * 144 + cc * 16, klb + go); \
            cpa16(base_ + A_VH + r * 144 + cc * 16, vhb + go); \
            cpa16(base_ + A_VL + r * 144 + cc * 16, vlb + go); \
        } \
        cpa_commit(); \
    } while (0)

    float o[8][4];
#pragma unroll
    for (int i = 0; i < 8; i++)
#pragma unroll
        for (int j = 0; j < 4; j++) o[i][j] = 0.f;
    float lacc[2] = {0.f, 0.f};

    KV_ISSUE(0, 0);

    for (int kt = 0; kt < S_ / 64; kt++) {
        const int s = kt & 1;
        const int k0 = kt * 64;

        __syncthreads();                      // prior compute on stage 1-s done
        if (kt + 1 < S_ / 64) { KV_ISSUE(1 - s, k0 + 64); cpa_wait1(); }
        else                  { cpa_wait0(); }
        __syncthreads();

        // mask words
        uint32_t mw[2][2];
#pragma unroll
        for (int i = 0; i < 2; i++) {
            int q = q0 + w * 16 + lr + i * 8;
            const unsigned* mp = g_mpk + ((long)b * S_ + q) * (S_ / 32) + (k0 >> 5);
            mw[i][0] = mp[0]; mw[i][1] = mp[1];
        }

        const uint32_t stb = sb + s * A_STG;
        const uint32_t kBH = stb + (lr8 + ((g >= 2) << 3)) * 144 + ((g & 1) << 4);
        const uint32_t kBL = kBH + A_KL;
        const uint32_t vBH = stb + A_VH + (lr8 + ((g & 1) << 3)) * 144 + ((g >> 1) << 4);
        const uint32_t vBL = vBH + (A_VL - A_VH);

        // ---- S = Q K^T ----
        float s_[8][4];
#pragma unroll
        for (int i = 0; i < 8; i++)
#pragma unroll
            for (int j = 0; j < 4; j++) s_[i][j] = 0.f;
#pragma unroll
        for (int ks = 0; ks < 4; ks++) {
#pragma unroll
            for (int np = 0; np < 4; np++) {
                uint32_t kb[4], kl4[4];
                ldsm4(kb,  kBH + np * 2304 + ks * 32);
                ldsm4(kl4, kBL + np * 2304 + ks * 32);
                mma_bf16(s_[np * 2],     qh[ks], kb);
                mma_bf16(s_[np * 2],     qh[ks], kl4);
                mma_bf16(s_[np * 2],     ql[ks], kb);
                mma_bf16(s_[np * 2 + 1], qh[ks], kb + 2);
                mma_bf16(s_[np * 2 + 1], qh[ks], kl4 + 2);
                mma_bf16(s_[np * 2 + 1], ql[ks], kb + 2);
            }
        }

        // ---- mask + exp2 (fixed max 0) ----
#pragma unroll
        for (int i = 0; i < 2; i++) {
#pragma unroll
            for (int na = 0; na < 8; na++) {
                uint32_t wbits = mw[i][na >> 2];
                int bit = (na & 3) * 8 + lc * 2;
                float v0 = ((wbits >> bit) & 1)       ? s_[na][i * 2] * SC     : 0.f;
                float v1 = ((wbits >> (bit + 1)) & 1) ? s_[na][i * 2 + 1] * SC : 0.f;
                float p0 = ex2(v0), p1 = ex2(v1);
                s_[na][i * 2] = p0; s_[na][i * 2 + 1] = p1;
                lacc[i] += p0 + p1;
            }
        }

        // ---- split P into A-frags ----
        uint32_t pah[4][4], pal[4][4];
#pragma unroll
        for (int ks = 0; ks < 4; ks++) {
            split_pack(s_[2 * ks][0],     s_[2 * ks][1],     pah[ks][0], pal[ks][0]);
            split_pack(s_[2 * ks][2],     s_[2 * ks][3],     pah[ks][1], pal[ks][1]);
            split_pack(s_[2 * ks + 1][0], s_[2 * ks + 1][1], pah[ks][2], pal[ks][2]);
            split_pack(s_[2 * ks + 1][2], s_[2 * ks + 1][3], pah[ks][3], pal[ks][3]);
        }

        // ---- O += P V ----
#pragma unroll
        for (int ks = 0; ks < 4; ks++) {
#pragma unroll
            for (int np = 0; np < 4; np++) {
                uint32_t vb[4], vl4[4];
                ldsm4t(vb,  vBH + ks * 2304 + np * 32);
                ldsm4t(vl4, vBL + ks * 2304 + np * 32);
                mma_bf16(o[np * 2],     pah[ks], vb);
                mma_bf16(o[np * 2],     pah[ks], vl4);
                mma_bf16(o[np * 2],     pal[ks], vb);
                mma_bf16(o[np * 2 + 1], pah[ks], vb + 2);
                mma_bf16(o[np * 2 + 1], pah[ks], vl4 + 2);
                mma_bf16(o[np * 2 + 1], pal[ks], vb + 2);
            }
        }
    }
#undef KV_ISSUE

    // ---- epilogue ----
#pragma unroll
    for (int i = 0; i < 2; i++) {
        lacc[i] += __shfl_xor_sync(0xffffffffu, lacc[i], 1);
        lacc[i] += __shfl_xor_sync(0xffffffffu, lacc[i], 2);
        float inv = 1.f / lacc[i];
        int q = q0 + w * 16 + lr + i * 8;
        __nv_bfloat16* zh = g_zh + ((long)b * S_ + q) * D_ + h * HD_;
        __nv_bfloat16* zl = g_zl + ((long)b * S_ + q) * D_ + h * HD_;
#pragma unroll
        for (int na = 0; na < 8; na++) {
            uint32_t hh, ll;
            split_pack(o[na][i * 2] * inv, o[na][i * 2 + 1] * inv, hh, ll);
            *(uint32_t*)(zh + na * 8 + lc * 2) = hh;
            *(uint32_t*)(zl + na * 8 + lc * 2) = ll;
        }
    }
}

// ---------------------------------------------------------------------------
extern "C" void kernel_launch(void* const* d_in, const int* in_sizes, int n_in,
                              void* d_out, int out_size)
{
    const float* xv   = (const float*)d_in[0];
    const float* xk   = (const float*)d_in[1];
    const float* xq   = (const float*)d_in[2];
    const int*   mask = (const int*)  d_in[3];
    const float* Wq   = (const float*)d_in[4];
    const float* bq   = (const float*)d_in[5];
    const float* Wk   = (const float*)d_in[6];
    const float* bk   = (const float*)d_in[7];
    const float* Wv   = (const float*)d_in[8];
    const float* bv   = (const float*)d_in[9];
    const float* Wo   = (const float*)d_in[10];
    const float* bo   = (const float*)d_in[11];
    float* out = (float*)d_out;

    cudaFuncSetAttribute(qkv_gemm,     cudaFuncAttributeMaxDynamicSharedMemorySize, GEMM_DSM);
    cudaFuncSetAttribute(outproj_gemm, cudaFuncAttributeMaxDynamicSharedMemorySize, GEMM_DSM);
    cudaFuncSetAttribute(attn_kernel,  cudaFuncAttributeMaxDynamicSharedMemorySize, ATT_DSM);

    const int nx4 = B_ * S_ * D_ / 4;
    const int nw4 = H_ * D_ * HD_ / 4;

    split_kernel<<<(nx4 + 255) / 256, 256>>>(xq, 0, nx4);
    split_kernel<<<(nx4 + 255) / 256, 256>>>(xk, 1, nx4);
    split_kernel<<<(nx4 + 255) / 256, 256>>>(xv, 2, nx4);
    split_kernel<<<(nw4 + 255) / 256, 256>>>(Wq, 3, nw4);
    split_kernel<<<(nw4 + 255) / 256, 256>>>(Wk, 4, nw4);
    split_kernel<<<(nw4 + 255) / 256, 256>>>(Wv, 5, nw4);
    split_kernel<<<(nw4 + 255) / 256, 256>>>(Wo, 6, nw4);
    pack_mask_kernel<<<(B_ * S_ * (S_ / 32) + 255) / 256, 256>>>(mask);

    qkv_gemm<<<dim3(S_ / 128, B_ * H_, 3), 256, GEMM_DSM>>>(bq, bk, bv);
    attn_kernel<<<dim3(S_ / 64, B_ * H_), 128, ATT_DSM>>>();
    outproj_gemm<<<dim3(D_ / 64, (B_ * S_) / 128), 256, GEMM_DSM>>>(bo, out);
}

// round 8
// speedup vs baseline: 1.1660x; 1.0208x over previous
#include <cuda_runtime.h>
#include <cuda_bf16.h>
#include <cstdint>

#define B_  4
#define S_  2048
#define D_  1024
#define H_  16
#define HD_ 64

// ---------------------------------------------------------------------------
// Static scratch (bf16 hi/lo split form everywhere), 16B-aligned for cp.async
// ---------------------------------------------------------------------------
__device__ __align__(16) __nv_bfloat16 g_xh[3][B_ * S_ * D_], g_xl[3][B_ * S_ * D_];
__device__ __align__(16) __nv_bfloat16 g_wh[3][H_ * D_ * HD_], g_wl[3][H_ * D_ * HD_];
__device__ __align__(16) __nv_bfloat16 g_woh[D_ * D_], g_wol[D_ * D_];
__device__ __align__(16) __nv_bfloat16 g_qh[B_*H_*S_*HD_], g_ql[B_*H_*S_*HD_];
__device__ __align__(16) __nv_bfloat16 g_kh[B_*H_*S_*HD_], g_kl[B_*H_*S_*HD_];
__device__ __align__(16) __nv_bfloat16 g_vh[B_*H_*S_*HD_], g_vl[B_*H_*S_*HD_];
__device__ __align__(16) __nv_bfloat16 g_zh[B_ * S_ * D_], g_zl[B_ * S_ * D_];
__device__ unsigned g_mpk[B_ * S_ * (S_ / 32)];

// ---------------------------------------------------------------------------
// Helpers
// ---------------------------------------------------------------------------
__device__ __forceinline__ uint32_t pack2(float x, float y) {
    __nv_bfloat162 t = __floats2bfloat162_rn(x, y);
    return *reinterpret_cast<uint32_t*>(&t);
}
__device__ __forceinline__ void split_pack(float x, float y, uint32_t& hi, uint32_t& lo) {
    float hx = __bfloat162float(__float2bfloat16(x));
    float hy = __bfloat162float(__float2bfloat16(y));
    hi = pack2(hx, hy);
    lo = pack2(x - hx, y - hy);
}
__device__ __forceinline__ float ex2(float x) {
    float y; asm("ex2.approx.f32 %0, %1;" : "=f"(y) : "f"(x)); return y;
}
__device__ __forceinline__ uint32_t smem_u32(const void* p) {
    return (uint32_t)__cvta_generic_to_shared(p);
}
__device__ __forceinline__ void ldsm4(uint32_t r[4], uint32_t a) {
    asm volatile("ldmatrix.sync.aligned.m8n8.x4.shared.b16 {%0,%1,%2,%3}, [%4];"
                 : "=r"(r[0]), "=r"(r[1]), "=r"(r[2]), "=r"(r[3]) : "r"(a));
}
__device__ __forceinline__ void ldsm4t(uint32_t r[4], uint32_t a) {
    asm volatile("ldmatrix.sync.aligned.m8n8.x4.trans.shared.b16 {%0,%1,%2,%3}, [%4];"
                 : "=r"(r[0]), "=r"(r[1]), "=r"(r[2]), "=r"(r[3]) : "r"(a));
}
__device__ __forceinline__ void mma_bf16(float c[4], const uint32_t a[4], const uint32_t b[2]) {
    asm volatile(
        "mma.sync.aligned.m16n8k16.row.col.f32.bf16.bf16.f32 "
        "{%0,%1,%2,%3}, {%4,%5,%6,%7}, {%8,%9}, {%0,%1,%2,%3};\n"
        : "+f"(c[0]), "+f"(c[1]), "+f"(c[2]), "+f"(c[3])
        : "r"(a[0]), "r"(a[1]), "r"(a[2]), "r"(a[3]), "r"(b[0]), "r"(b[1]));
}
__device__ __forceinline__ void cpa16(uint32_t saddr, const void* g) {
    asm volatile("cp.async.cg.shared.global [%0], [%1], 16;" :: "r"(saddr), "l"(g) : "memory");
}
__device__ __forceinline__ void cpa_commit() { asm volatile("cp.async.commit_group;" ::: "memory"); }
__device__ __forceinline__ void cpa_wait0()  { asm volatile("cp.async.wait_group 0;" ::: "memory"); }
__device__ __forceinline__ void cpa_wait1()  { asm volatile("cp.async.wait_group 1;" ::: "memory"); }

// ---------------------------------------------------------------------------
// Fused split kernels
// ---------------------------------------------------------------------------
__global__ void split_x_kernel(const float* __restrict__ xq, const float* __restrict__ xk,
                               const float* __restrict__ xv)
{
    const int which = blockIdx.x >> 13;                  // 3 x 8192 blocks
    const int i = (blockIdx.x & 8191) * 256 + threadIdx.x;
    const float* in = (which == 0) ? xq : (which == 1) ? xk : xv;
    float4 v = ((const float4*)in)[i];
    uint32_t h0, l0, h1, l1;
    split_pack(v.x, v.y, h0, l0);
    split_pack(v.z, v.w, h1, l1);
    ((uint2*)g_xh[which])[i] = make_uint2(h0, h1);
    ((uint2*)g_xl[which])[i] = make_uint2(l0, l1);
}

__global__ void split_w_kernel(const float* __restrict__ Wq, const float* __restrict__ Wk,
                               const float* __restrict__ Wv, const float* __restrict__ Wo)
{
    const int dst = blockIdx.x >> 10;                    // 4 x 1024 blocks
    const int i = (blockIdx.x & 1023) * 256 + threadIdx.x;
    const float* in = (dst == 0) ? Wq : (dst == 1) ? Wk : (dst == 2) ? Wv : Wo;
    __nv_bfloat16* hi = (dst < 3) ? g_wh[dst] : g_woh;
    __nv_bfloat16* lo = (dst < 3) ? g_wl[dst] : g_wol;
    float4 v = ((const float4*)in)[i];
    uint32_t h0, l0, h1, l1;
    split_pack(v.x, v.y, h0, l0);
    split_pack(v.z, v.w, h1, l1);
    ((uint2*)hi)[i] = make_uint2(h0, h1);
    ((uint2*)lo)[i] = make_uint2(l0, l1);
}

__global__ void pack_mask_kernel(const int* __restrict__ mask)
{
    int i = blockIdx.x * 256 + threadIdx.x;
    if (i >= B_ * S_ * (S_ / 32)) return;
    const int4* mp = (const int4*)(mask + (long)i * 32);
    unsigned w = 0;
#pragma unroll
    for (int j = 0; j < 8; j++) {
        int4 m = mp[j];
        w |= (unsigned)(m.x != 0) << (j * 4 + 0);
        w |= (unsigned)(m.y != 0) << (j * 4 + 1);
        w |= (unsigned)(m.z != 0) << (j * 4 + 2);
        w |= (unsigned)(m.w != 0) << (j * 4 + 3);
    }
    g_mpk[i] = w;
}

__global__ void noop_kernel() {}

// ---------------------------------------------------------------------------
// GEMM: 128(m) x 128(n) x kdim, k-chunks of 32, 2-stage cp.async pipeline.
// 256 threads = 8 warps (4m x 2n), warp tile 32x64.
// Head-strided B addressing: src(k, col) = Bg + (col>>6)*bHS + k*ldb + (col&63)
//   qkv:     bHS = D*HD, ldb = 64    (2 heads per n-tile)
//   outproj: bHS = 64,   ldb = D
// Stage (37888 B): Ah[128x80] Al[128x80] Bh[32x272] Bl[32x272]
// ---------------------------------------------------------------------------
#define G_STG   37888
#define G_AL    10240
#define G_BH    20480
#define G_BL    29184
#define GEMM_DSM (2 * G_STG)

template<bool SPLIT_OUT>
__device__ __forceinline__ void gemm_body(
    const __nv_bfloat16* __restrict__ Agh, const __nv_bfloat16* __restrict__ Agl,
    int lda, int kdim,
    const __nv_bfloat16* __restrict__ Bgh, const __nv_bfloat16* __restrict__ Bgl,
    long bHS, int ldb,
    const float* __restrict__ bias,
    float* __restrict__ outF, int ldoF,
    __nv_bfloat16* __restrict__ outH, __nv_bfloat16* __restrict__ outL, long outHS)
{
    extern __shared__ uint8_t dyn[];
    const uint32_t sb = smem_u32(dyn);

    const int t = threadIdx.x, lane = t & 31, warp = t >> 5;
    const int wm = warp >> 1, wn = warp & 1;
    const int lr = lane >> 2, lc = lane & 3;
    const int g = lane >> 3, lr8 = lane & 7;

    float c[2][8][4];
#pragma unroll
    for (int i = 0; i < 2; i++)
#pragma unroll
        for (int j = 0; j < 8; j++)
#pragma unroll
            for (int k = 0; k < 4; k++) c[i][j][k] = 0.f;

#define G_ISSUE(stg, k0) do { \
        uint32_t base_ = sb + (stg) * G_STG; \
        _Pragma("unroll") \
        for (int j = 0; j < 2; j++) { \
            int idx = t + j * 256, r = idx >> 2, cc = idx & 3; \
            cpa16(base_ + r * 80 + cc * 16,         Agh + (long)r * lda + (k0) + cc * 8); \
            cpa16(base_ + G_AL + r * 80 + cc * 16,  Agl + (long)r * lda + (k0) + cc * 8); \
        } \
        _Pragma("unroll") \
        for (int j = 0; j < 2; j++) { \
            int idx = t + j * 256, r = idx >> 4, n16 = idx & 15; \
            long src = (long)(n16 >> 3) * bHS + (long)((k0) + r) * ldb + (n16 & 7) * 8; \
            cpa16(base_ + G_BH + r * 272 + n16 * 16, Bgh + src); \
            cpa16(base_ + G_BL + r * 272 + n16 * 16, Bgl + src); \
        } \
        cpa_commit(); \
    } while (0)

    G_ISSUE(0, 0);
    const int nchunks = kdim / 32;
    for (int ch = 0; ch < nchunks; ch++) {
        const int s = ch & 1;
        __syncthreads();
        if (ch + 1 < nchunks) { G_ISSUE(1 - s, (ch + 1) * 32); cpa_wait1(); }
        else                  { cpa_wait0(); }
        __syncthreads();

        const uint32_t stb = sb + s * G_STG;
        const uint32_t aBH = stb + (wm * 32 + lr8 + ((g & 1) << 3)) * 80 + ((g >> 1) << 4);
        const uint32_t aBL = aBH + G_AL;
        const uint32_t bBH = stb + G_BH + (lr8 + ((g & 1) << 3)) * 272 + wn * 128 + ((g >> 1) << 4);
        const uint32_t bBL = bBH + (G_BL - G_BH);

#pragma unroll
        for (int ks = 0; ks < 2; ks++) {
            uint32_t ah[2][4], al[2][4];
#pragma unroll
            for (int ma = 0; ma < 2; ma++) {
                ldsm4(ah[ma], aBH + ma * 1280 + ks * 32);
                ldsm4(al[ma], aBL + ma * 1280 + ks * 32);
            }
#pragma unroll
            for (int np = 0; np < 4; np++) {
                uint32_t bh4[4], bl4[4];
                ldsm4t(bh4, bBH + ks * 4352 + np * 32);   // k16 step = 16 rows x 272B
                ldsm4t(bl4, bBL + ks * 4352 + np * 32);
#pragma unroll
                for (int ma = 0; ma < 2; ma++) {
                    mma_bf16(c[ma][np * 2],     ah[ma], bh4);
                    mma_bf16(c[ma][np * 2],     ah[ma], bl4);
                    mma_bf16(c[ma][np * 2],     al[ma], bh4);
                    mma_bf16(c[ma][np * 2 + 1], ah[ma], bh4 + 2);
                    mma_bf16(c[ma][np * 2 + 1], ah[ma], bl4 + 2);
                    mma_bf16(c[ma][np * 2 + 1], al[ma], bh4 + 2);
                }
            }
        }
    }
#undef G_ISSUE

    // epilogue
#pragma unroll
    for (int ma = 0; ma < 2; ma++) {
#pragma unroll
        for (int na = 0; na < 8; na++) {
            int r   = wm * 32 + ma * 16 + lr;
            int col = wn * 64 + na * 8 + lc * 2;
            float b0 = bias[col], b1 = bias[col + 1];
            float v00 = c[ma][na][0] + b0, v01 = c[ma][na][1] + b1;
            float v10 = c[ma][na][2] + b0, v11 = c[ma][na][3] + b1;
            if (SPLIT_OUT) {
                int head = col >> 6, e = col & 63;
                __nv_bfloat16* ph = outH + head * outHS + (long)r * 64 + e;
                __nv_bfloat16* pl = outL + head * outHS + (long)r * 64 + e;
                uint32_t hh, ll;
                split_pack(v00, v01, hh, ll);
                *(uint32_t*)ph = hh; *(uint32_t*)pl = ll;
                split_pack(v10, v11, hh, ll);
                *(uint32_t*)(ph + 8 * 64) = hh; *(uint32_t*)(pl + 8 * 64) = ll;
            } else {
                *(float2*)(outF + (long)r * ldoF + col)       = make_float2(v00, v01);
                *(float2*)(outF + (long)(r + 8) * ldoF + col) = make_float2(v10, v11);
            }
        }
    }
}

__global__ __launch_bounds__(256, 2) void qkv_gemm(
    const float* __restrict__ bq, const float* __restrict__ bk, const float* __restrict__ bv)
{
    const int which = blockIdx.z;
    const int h0 = blockIdx.x * 2;
    const int b  = blockIdx.y >> 4;
    const int s0 = (blockIdx.y & 15) * 128;

    const __nv_bfloat16* Agh = g_xh[which] + ((long)b * S_ + s0) * D_;
    const __nv_bfloat16* Agl = g_xl[which] + ((long)b * S_ + s0) * D_;
    const __nv_bfloat16* Bgh = g_wh[which] + (long)h0 * D_ * HD_;
    const __nv_bfloat16* Bgl = g_wl[which] + (long)h0 * D_ * HD_;
    const float* bias = ((which == 0) ? bq : (which == 1) ? bk : bv) + h0 * HD_;

    long ob = ((long)(b * H_ + h0) * S_ + s0) * HD_;
    __nv_bfloat16* oh = ((which == 0) ? g_qh : (which == 1) ? g_kh : g_vh) + ob;
    __nv_bfloat16* ol = ((which == 0) ? g_ql : (which == 1) ? g_kl : g_vl) + ob;

    gemm_body<true>(Agh, Agl, D_, D_, Bgh, Bgl, (long)D_ * HD_, HD_,
                    bias, nullptr, 0, oh, ol, (long)S_ * HD_);
}

__global__ __launch_bounds__(256, 2) void outproj_gemm(
    const float* __restrict__ bo, float* __restrict__ out)
{
    const int n0 = blockIdx.x * 128;
    const long m0 = (long)blockIdx.y * 128;
    gemm_body<false>(g_zh + m0 * D_, g_zl + m0 * D_, D_, D_,
                     g_woh + n0, g_wol + n0, 64, D_,
                     bo + n0, out + m0 * D_ + n0, D_, nullptr, nullptr, 0);
}

// ---------------------------------------------------------------------------
// Flash attention (R7, proven): 64 q-rows/block, 128 thr = 4 warps,
// 2-stage cp.async pipeline (K+V one group). Stage 36864 B.
// ---------------------------------------------------------------------------
#define A_STG  36864
#define A_KL   9216
#define A_VH   18432
#define A_VL   27648
#define ATT_DSM (2 * A_STG)

__global__ __launch_bounds__(128) void attn_kernel()
{
    extern __shared__ uint8_t dyn[];
    const uint32_t sb = smem_u32(dyn);

    const int t = threadIdx.x, lane = t & 31, w = t >> 5;
    const int lr = lane >> 2, lc = lane & 3;
    const int g = lane >> 3, lr8 = lane & 7;
    const int bh = blockIdx.y, b = bh >> 4, h = bh & 15;
    const int q0 = blockIdx.x * 64;

    const __nv_bfloat16* qgh = g_qh + ((long)bh * S_ + q0) * HD_;
    const __nv_bfloat16* qgl = g_ql + ((long)bh * S_ + q0) * HD_;
    const __nv_bfloat16* khb = g_kh + (long)bh * S_ * HD_;
    const __nv_bfloat16* klb = g_kl + (long)bh * S_ * HD_;
    const __nv_bfloat16* vhb = g_vh + (long)bh * S_ * HD_;
    const __nv_bfloat16* vlb = g_vl + (long)bh * S_ * HD_;
    const float SC = 0.125f * 1.44269504088896340736f;

#pragma unroll
    for (int j = 0; j < 4; j++) {
        int idx = t + j * 128, r = idx >> 3, cc = idx & 7;
        cpa16(sb + A_STG + r * 144 + cc * 16,        qgh + (long)r * HD_ + cc * 8);
        cpa16(sb + A_STG + A_KL + r * 144 + cc * 16, qgl + (long)r * HD_ + cc * 8);
    }
    cpa_commit();
    cpa_wait0();
    __syncthreads();

    uint32_t qh[4][4], ql[4][4];
    {
        uint32_t qBH = sb + A_STG + (w * 16 + lr8 + ((g & 1) << 3)) * 144 + ((g >> 1) << 4);
        uint32_t qBL = qBH + A_KL;
#pragma unroll
        for (int ks = 0; ks < 4; ks++) {
            ldsm4(qh[ks], qBH + ks * 32);
            ldsm4(ql[ks], qBL + ks * 32);
        }
    }
    __syncthreads();

#define KV_ISSUE(stg, k0) do { \
        uint32_t base_ = sb + (stg) * A_STG; \
        _Pragma("unroll") \
        for (int j = 0; j < 4; j++) { \
            int idx = t + j * 128, r = idx >> 3, cc = idx & 7; \
            long go = (long)((k0) + r) * HD_ + cc * 8; \
            cpa16(base_ + r * 144 + cc * 16,        khb + go); \
            cpa16(base_ + A_KL + r * 144 + cc * 16, klb + go); \
            cpa16(base_ + A_VH + r * 144 + cc * 16, vhb + go); \
            cpa16(base_ + A_VL + r * 144 + cc * 16, vlb + go); \
        } \
        cpa_commit(); \
    } while (0)

    float o[8][4];
#pragma unroll
    for (int i = 0; i < 8; i++)
#pragma unroll
        for (int j = 0; j < 4; j++) o[i][j] = 0.f;
    float lacc[2] = {0.f, 0.f};

    KV_ISSUE(0, 0);

    for (int kt = 0; kt < S_ / 64; kt++) {
        const int s = kt & 1;
        const int k0 = kt * 64;

        __syncthreads();
        if (kt + 1 < S_ / 64) { KV_ISSUE(1 - s, k0 + 64); cpa_wait1(); }
        else                  { cpa_wait0(); }
        __syncthreads();

        uint32_t mw[2][2];
#pragma unroll
        for (int i = 0; i < 2; i++) {
            int q = q0 + w * 16 + lr + i * 8;
            const unsigned* mp = g_mpk + ((long)b * S_ + q) * (S_ / 32) + (k0 >> 5);
            mw[i][0] = mp[0]; mw[i][1] = mp[1];
        }

        const uint32_t stb = sb + s * A_STG;
        const uint32_t kBH = stb + (lr8 + ((g >= 2) << 3)) * 144 + ((g & 1) << 4);
        const uint32_t kBL = kBH + A_KL;
        const uint32_t vBH = stb + A_VH + (lr8 + ((g & 1) << 3)) * 144 + ((g >> 1) << 4);
        const uint32_t vBL = vBH + (A_VL - A_VH);

        float s_[8][4];
#pragma unroll
        for (int i = 0; i < 8; i++)
#pragma unroll
            for (int j = 0; j < 4; j++) s_[i][j] = 0.f;
#pragma unroll
        for (int ks = 0; ks < 4; ks++) {
#pragma unroll
            for (int np = 0; np < 4; np++) {
                uint32_t kb[4], kl4[4];
                ldsm4(kb,  kBH + np * 2304 + ks * 32);
                ldsm4(kl4, kBL + np * 2304 + ks * 32);
                mma_bf16(s_[np * 2],     qh[ks], kb);
                mma_bf16(s_[np * 2],     qh[ks], kl4);
                mma_bf16(s_[np * 2],     ql[ks], kb);
                mma_bf16(s_[np * 2 + 1], qh[ks], kb + 2);
                mma_bf16(s_[np * 2 + 1], qh[ks], kl4 + 2);
                mma_bf16(s_[np * 2 + 1], ql[ks], kb + 2);
            }
        }

#pragma unroll
        for (int i = 0; i < 2; i++) {
#pragma unroll
            for (int na = 0; na < 8; na++) {
                uint32_t wbits = mw[i][na >> 2];
                int bit = (na & 3) * 8 + lc * 2;
                float v0 = ((wbits >> bit) & 1)       ? s_[na][i * 2] * SC     : 0.f;
                float v1 = ((wbits >> (bit + 1)) & 1) ? s_[na][i * 2 + 1] * SC : 0.f;
                float p0 = ex2(v0), p1 = ex2(v1);
                s_[na][i * 2] = p0; s_[na][i * 2 + 1] = p1;
                lacc[i] += p0 + p1;
            }
        }

        uint32_t pah[4][4], pal[4][4];
#pragma unroll
        for (int ks = 0; ks < 4; ks++) {
            split_pack(s_[2 * ks][0],     s_[2 * ks][1],     pah[ks][0], pal[ks][0]);
            split_pack(s_[2 * ks][2],     s_[2 * ks][3],     pah[ks][1], pal[ks][1]);
            split_pack(s_[2 * ks + 1][0], s_[2 * ks + 1][1], pah[ks][2], pal[ks][2]);
            split_pack(s_[2 * ks + 1][2], s_[2 * ks + 1][3], pah[ks][3], pal[ks][3]);
        }

#pragma unroll
        for (int ks = 0; ks < 4; ks++) {
#pragma unroll
            for (int np = 0; np < 4; np++) {
                uint32_t vb[4], vl4[4];
                ldsm4t(vb,  vBH + ks * 2304 + np * 32);
                ldsm4t(vl4, vBL + ks * 2304 + np * 32);
                mma_bf16(o[np * 2],     pah[ks], vb);
                mma_bf16(o[np * 2],     pah[ks], vl4);
                mma_bf16(o[np * 2],     pal[ks], vb);
                mma_bf16(o[np * 2 + 1], pah[ks], vb + 2);
                mma_bf16(o[np * 2 + 1], pah[ks], vl4 + 2);
                mma_bf16(o[np * 2 + 1], pal[ks], vb + 2);
            }
        }
    }
#undef KV_ISSUE

#pragma unroll
    for (int i = 0; i < 2; i++) {
        lacc[i] += __shfl_xor_sync(0xffffffffu, lacc[i], 1);
        lacc[i] += __shfl_xor_sync(0xffffffffu, lacc[i], 2);
        float inv = 1.f / lacc[i];
        int q = q0 + w * 16 + lr + i * 8;
        __nv_bfloat16* zh = g_zh + ((long)b * S_ + q) * D_ + h * HD_;
        __nv_bfloat16* zl = g_zl + ((long)b * S_ + q) * D_ + h * HD_;
#pragma unroll
        for (int na = 0; na < 8; na++) {
            uint32_t hh, ll;
            split_pack(o[na][i * 2] * inv, o[na][i * 2 + 1] * inv, hh, ll);
            *(uint32_t*)(zh + na * 8 + lc * 2) = hh;
            *(uint32_t*)(zl + na * 8 + lc * 2) = ll;
        }
    }
}

// ---------------------------------------------------------------------------
extern "C" void kernel_launch(void* const* d_in, const int* in_sizes, int n_in,
                              void* d_out, int out_size)
{
    const float* xv   = (const float*)d_in[0];
    const float* xk   = (const float*)d_in[1];
    const float* xq   = (const float*)d_in[2];
    const int*   mask = (const int*)  d_in[3];
    const float* Wq   = (const float*)d_in[4];
    const float* bq   = (const float*)d_in[5];
    const float* Wk   = (const float*)d_in[6];
    const float* bk   = (const float*)d_in[7];
    const float* Wv   = (const float*)d_in[8];
    const float* bv   = (const float*)d_in[9];
    const float* Wo   = (const float*)d_in[10];
    const float* bo   = (const float*)d_in[11];
    float* out = (float*)d_out;

    cudaFuncSetAttribute(qkv_gemm,     cudaFuncAttributeMaxDynamicSharedMemorySize, GEMM_DSM);
    cudaFuncSetAttribute(outproj_gemm, cudaFuncAttributeMaxDynamicSharedMemorySize, GEMM_DSM);
    cudaFuncSetAttribute(attn_kernel,  cudaFuncAttributeMaxDynamicSharedMemorySize, ATT_DSM);

    // Launch order places attn_kernel at global launch index 6 (ncu -s 5 -c 1).
    split_x_kernel<<<3 * 8192, 256>>>(xq, xk, xv);
    split_w_kernel<<<4 * 1024, 256>>>(Wq, Wk, Wv, Wo);
    pack_mask_kernel<<<(B_ * S_ * (S_ / 32) + 255) / 256, 256>>>(mask);
    noop_kernel<<<1, 32>>>();
    qkv_gemm<<<dim3(H_ / 2, 64, 3), 256, GEMM_DSM>>>(bq, bk, bv);
    attn_kernel<<<dim3(S_ / 64, B_ * H_), 128, ATT_DSM>>>();
    outproj_gemm<<<dim3(D_ / 128, (B_ * S_) / 128), 256, GEMM_DSM>>>(bo, out);
}

// round 9
// speedup vs baseline: 1.2068x; 1.0350x over previous
#include <cuda_runtime.h>
#include <cuda_bf16.h>
#include <cstdint>

#define B_  4
#define S_  2048
#define D_  1024
#define H_  16
#define HD_ 64

// ---------------------------------------------------------------------------
// Static scratch (bf16 hi/lo split form everywhere), 16B-aligned for cp.async
// ---------------------------------------------------------------------------
__device__ __align__(16) __nv_bfloat16 g_xh[3][B_ * S_ * D_], g_xl[3][B_ * S_ * D_];
__device__ __align__(16) __nv_bfloat16 g_wh[3][H_ * D_ * HD_], g_wl[3][H_ * D_ * HD_];
__device__ __align__(16) __nv_bfloat16 g_woh[D_ * D_], g_wol[D_ * D_];
__device__ __align__(16) __nv_bfloat16 g_qh[B_*H_*S_*HD_], g_ql[B_*H_*S_*HD_];
__device__ __align__(16) __nv_bfloat16 g_kh[B_*H_*S_*HD_], g_kl[B_*H_*S_*HD_];
__device__ __align__(16) __nv_bfloat16 g_vh[B_*H_*S_*HD_], g_vl[B_*H_*S_*HD_];
__device__ __align__(16) __nv_bfloat16 g_zh[B_ * S_ * D_], g_zl[B_ * S_ * D_];
__device__ unsigned g_mpk[B_ * S_ * (S_ / 32)];

// ---------------------------------------------------------------------------
// Helpers
// ---------------------------------------------------------------------------
__device__ __forceinline__ uint32_t pack2(float x, float y) {
    __nv_bfloat162 t = __floats2bfloat162_rn(x, y);
    return *reinterpret_cast<uint32_t*>(&t);
}
__device__ __forceinline__ void split_pack(float x, float y, uint32_t& hi, uint32_t& lo) {
    float hx = __bfloat162float(__float2bfloat16(x));
    float hy = __bfloat162float(__float2bfloat16(y));
    hi = pack2(hx, hy);
    lo = pack2(x - hx, y - hy);
}
__device__ __forceinline__ float ex2(float x) {
    float y; asm("ex2.approx.f32 %0, %1;" : "=f"(y) : "f"(x)); return y;
}
__device__ __forceinline__ uint32_t smem_u32(const void* p) {
    return (uint32_t)__cvta_generic_to_shared(p);
}
__device__ __forceinline__ void ldsm4(uint32_t r[4], uint32_t a) {
    asm volatile("ldmatrix.sync.aligned.m8n8.x4.shared.b16 {%0,%1,%2,%3}, [%4];"
                 : "=r"(r[0]), "=r"(r[1]), "=r"(r[2]), "=r"(r[3]) : "r"(a));
}
__device__ __forceinline__ void ldsm4t(uint32_t r[4], uint32_t a) {
    asm volatile("ldmatrix.sync.aligned.m8n8.x4.trans.shared.b16 {%0,%1,%2,%3}, [%4];"
                 : "=r"(r[0]), "=r"(r[1]), "=r"(r[2]), "=r"(r[3]) : "r"(a));
}
__device__ __forceinline__ void mma_bf16(float c[4], const uint32_t a[4], const uint32_t b[2]) {
    asm volatile(
        "mma.sync.aligned.m16n8k16.row.col.f32.bf16.bf16.f32 "
        "{%0,%1,%2,%3}, {%4,%5,%6,%7}, {%8,%9}, {%0,%1,%2,%3};\n"
        : "+f"(c[0]), "+f"(c[1]), "+f"(c[2]), "+f"(c[3])
        : "r"(a[0]), "r"(a[1]), "r"(a[2]), "r"(a[3]), "r"(b[0]), "r"(b[1]));
}
__device__ __forceinline__ void cpa16(uint32_t saddr, const void* g) {
    asm volatile("cp.async.cg.shared.global [%0], [%1], 16;" :: "r"(saddr), "l"(g) : "memory");
}
__device__ __forceinline__ void cpa_commit() { asm volatile("cp.async.commit_group;" ::: "memory"); }
__device__ __forceinline__ void cpa_wait0()  { asm volatile("cp.async.wait_group 0;" ::: "memory"); }
__device__ __forceinline__ void cpa_wait1()  { asm volatile("cp.async.wait_group 1;" ::: "memory"); }

// ---------------------------------------------------------------------------
// Fused split kernels
// ---------------------------------------------------------------------------
__global__ void split_x_kernel(const float* __restrict__ xq, const float* __restrict__ xk,
                               const float* __restrict__ xv)
{
    const int which = blockIdx.x >> 13;
    const int i = (blockIdx.x & 8191) * 256 + threadIdx.x;
    const float* in = (which == 0) ? xq : (which == 1) ? xk : xv;
    float4 v = ((const float4*)in)[i];
    uint32_t h0, l0, h1, l1;
    split_pack(v.x, v.y, h0, l0);
    split_pack(v.z, v.w, h1, l1);
    ((uint2*)g_xh[which])[i] = make_uint2(h0, h1);
    ((uint2*)g_xl[which])[i] = make_uint2(l0, l1);
}

__global__ void split_w_kernel(const float* __restrict__ Wq, const float* __restrict__ Wk,
                               const float* __restrict__ Wv, const float* __restrict__ Wo)
{
    const int dst = blockIdx.x >> 10;
    const int i = (blockIdx.x & 1023) * 256 + threadIdx.x;
    const float* in = (dst == 0) ? Wq : (dst == 1) ? Wk : (dst == 2) ? Wv : Wo;
    __nv_bfloat16* hi = (dst < 3) ? g_wh[dst] : g_woh;
    __nv_bfloat16* lo = (dst < 3) ? g_wl[dst] : g_wol;
    float4 v = ((const float4*)in)[i];
    uint32_t h0, l0, h1, l1;
    split_pack(v.x, v.y, h0, l0);
    split_pack(v.z, v.w, h1, l1);
    ((uint2*)hi)[i] = make_uint2(h0, h1);
    ((uint2*)lo)[i] = make_uint2(l0, l1);
}

__global__ void pack_mask_kernel(const int* __restrict__ mask)
{
    int i = blockIdx.x * 256 + threadIdx.x;
    if (i >= B_ * S_ * (S_ / 32)) return;
    const int4* mp = (const int4*)(mask + (long)i * 32);
    unsigned w = 0;
#pragma unroll
    for (int j = 0; j < 8; j++) {
        int4 m = mp[j];
        w |= (unsigned)(m.x != 0) << (j * 4 + 0);
        w |= (unsigned)(m.y != 0) << (j * 4 + 1);
        w |= (unsigned)(m.z != 0) << (j * 4 + 2);
        w |= (unsigned)(m.w != 0) << (j * 4 + 3);
    }
    g_mpk[i] = w;
}

// ---------------------------------------------------------------------------
// GEMM: 128(m) x 128(n) x kdim, k-chunks of 32, 2-stage cp.async pipeline.
// (unchanged from R8 — proven)
// ---------------------------------------------------------------------------
#define G_STG   37888
#define G_AL    10240
#define G_BH    20480
#define G_BL    29184
#define GEMM_DSM (2 * G_STG)

template<bool SPLIT_OUT>
__device__ __forceinline__ void gemm_body(
    const __nv_bfloat16* __restrict__ Agh, const __nv_bfloat16* __restrict__ Agl,
    int lda, int kdim,
    const __nv_bfloat16* __restrict__ Bgh, const __nv_bfloat16* __restrict__ Bgl,
    long bHS, int ldb,
    const float* __restrict__ bias,
    float* __restrict__ outF, int ldoF,
    __nv_bfloat16* __restrict__ outH, __nv_bfloat16* __restrict__ outL, long outHS)
{
    extern __shared__ uint8_t dyn[];
    const uint32_t sb = smem_u32(dyn);

    const int t = threadIdx.x, lane = t & 31, warp = t >> 5;
    const int wm = warp >> 1, wn = warp & 1;
    const int lr = lane >> 2, lc = lane & 3;
    const int g = lane >> 3, lr8 = lane & 7;

    float c[2][8][4];
#pragma unroll
    for (int i = 0; i < 2; i++)
#pragma unroll
        for (int j = 0; j < 8; j++)
#pragma unroll
            for (int k = 0; k < 4; k++) c[i][j][k] = 0.f;

#define G_ISSUE(stg, k0) do { \
        uint32_t base_ = sb + (stg) * G_STG; \
        _Pragma("unroll") \
        for (int j = 0; j < 2; j++) { \
            int idx = t + j * 256, r = idx >> 2, cc = idx & 3; \
            cpa16(base_ + r * 80 + cc * 16,         Agh + (long)r * lda + (k0) + cc * 8); \
            cpa16(base_ + G_AL + r * 80 + cc * 16,  Agl + (long)r * lda + (k0) + cc * 8); \
        } \
        _Pragma("unroll") \
        for (int j = 0; j < 2; j++) { \
            int idx = t + j * 256, r = idx >> 4, n16 = idx & 15; \
            long src = (long)(n16 >> 3) * bHS + (long)((k0) + r) * ldb + (n16 & 7) * 8; \
            cpa16(base_ + G_BH + r * 272 + n16 * 16, Bgh + src); \
            cpa16(base_ + G_BL + r * 272 + n16 * 16, Bgl + src); \
        } \
        cpa_commit(); \
    } while (0)

    G_ISSUE(0, 0);
    const int nchunks = kdim / 32;
    for (int ch = 0; ch < nchunks; ch++) {
        const int s = ch & 1;
        __syncthreads();
        if (ch + 1 < nchunks) { G_ISSUE(1 - s, (ch + 1) * 32); cpa_wait1(); }
        else                  { cpa_wait0(); }
        __syncthreads();

        const uint32_t stb = sb + s * G_STG;
        const uint32_t aBH = stb + (wm * 32 + lr8 + ((g & 1) << 3)) * 80 + ((g >> 1) << 4);
        const uint32_t aBL = aBH + G_AL;
        const uint32_t bBH = stb + G_BH + (lr8 + ((g & 1) << 3)) * 272 + wn * 128 + ((g >> 1) << 4);
        const uint32_t bBL = bBH + (G_BL - G_BH);

#pragma unroll
        for (int ks = 0; ks < 2; ks++) {
            uint32_t ah[2][4], al[2][4];
#pragma unroll
            for (int ma = 0; ma < 2; ma++) {
                ldsm4(ah[ma], aBH + ma * 1280 + ks * 32);
                ldsm4(al[ma], aBL + ma * 1280 + ks * 32);
            }
#pragma unroll
            for (int np = 0; np < 4; np++) {
                uint32_t bh4[4], bl4[4];
                ldsm4t(bh4, bBH + ks * 4352 + np * 32);
                ldsm4t(bl4, bBL + ks * 4352 + np * 32);
#pragma unroll
                for (int ma = 0; ma < 2; ma++) {
                    mma_bf16(c[ma][np * 2],     ah[ma], bh4);
                    mma_bf16(c[ma][np * 2],     ah[ma], bl4);
                    mma_bf16(c[ma][np * 2],     al[ma], bh4);
                    mma_bf16(c[ma][np * 2 + 1], ah[ma], bh4 + 2);
                    mma_bf16(c[ma][np * 2 + 1], ah[ma], bl4 + 2);
                    mma_bf16(c[ma][np * 2 + 1], al[ma], bh4 + 2);
                }
            }
        }
    }
#undef G_ISSUE

#pragma unroll
    for (int ma = 0; ma < 2; ma++) {
#pragma unroll
        for (int na = 0; na < 8; na++) {
            int r   = wm * 32 + ma * 16 + lr;
            int col = wn * 64 + na * 8 + lc * 2;
            float b0 = bias[col], b1 = bias[col + 1];
            float v00 = c[ma][na][0] + b0, v01 = c[ma][na][1] + b1;
            float v10 = c[ma][na][2] + b0, v11 = c[ma][na][3] + b1;
            if (SPLIT_OUT) {
                int head = col >> 6, e = col & 63;
                __nv_bfloat16* ph = outH + head * outHS + (long)r * 64 + e;
                __nv_bfloat16* pl = outL + head * outHS + (long)r * 64 + e;
                uint32_t hh, ll;
                split_pack(v00, v01, hh, ll);
                *(uint32_t*)ph = hh; *(uint32_t*)pl = ll;
                split_pack(v10, v11, hh, ll);
                *(uint32_t*)(ph + 8 * 64) = hh; *(uint32_t*)(pl + 8 * 64) = ll;
            } else {
                *(float2*)(outF + (long)r * ldoF + col)       = make_float2(v00, v01);
                *(float2*)(outF + (long)(r + 8) * ldoF + col) = make_float2(v10, v11);
            }
        }
    }
}

__global__ __launch_bounds__(256, 2) void qkv_gemm(
    const float* __restrict__ bq, const float* __restrict__ bk, const float* __restrict__ bv)
{
    const int which = blockIdx.z;
    const int h0 = blockIdx.x * 2;
    const int b  = blockIdx.y >> 4;
    const int s0 = (blockIdx.y & 15) * 128;

    const __nv_bfloat16* Agh = g_xh[which] + ((long)b * S_ + s0) * D_;
    const __nv_bfloat16* Agl = g_xl[which] + ((long)b * S_ + s0) * D_;
    const __nv_bfloat16* Bgh = g_wh[which] + (long)h0 * D_ * HD_;
    const __nv_bfloat16* Bgl = g_wl[which] + (long)h0 * D_ * HD_;
    const float* bias = ((which == 0) ? bq : (which == 1) ? bk : bv) + h0 * HD_;

    long ob = ((long)(b * H_ + h0) * S_ + s0) * HD_;
    __nv_bfloat16* oh = ((which == 0) ? g_qh : (which == 1) ? g_kh : g_vh) + ob;
    __nv_bfloat16* ol = ((which == 0) ? g_ql : (which == 1) ? g_kl : g_vl) + ob;

    gemm_body<true>(Agh, Agl, D_, D_, Bgh, Bgl, (long)D_ * HD_, HD_,
                    bias, nullptr, 0, oh, ol, (long)S_ * HD_);
}

__global__ __launch_bounds__(256, 2) void outproj_gemm(
    const float* __restrict__ bo, float* __restrict__ out)
{
    const int n0 = blockIdx.x * 128;
    const long m0 = (long)blockIdx.y * 128;
    gemm_body<false>(g_zh + m0 * D_, g_zl + m0 * D_, D_, D_,
                     g_woh + n0, g_wol + n0, 64, D_,
                     bo + n0, out + m0 * D_ + n0, D_, nullptr, nullptr, 0);
}

// ---------------------------------------------------------------------------
// Flash attention: 128 q-rows/block, 256 thr = 8 warps (16 q-rows each),
// 64-key tiles, 2-stage cp.async (K+V one group). Stage 36864 B.
// Q pre-staged across the FULL stage-1 buffer (warps 0-3 in K area,
// warps 4-7 in V area), then per-tile compute identical to R7 per warp.
// ---------------------------------------------------------------------------
#define A_STG  36864
#define A_KL   9216
#define A_VH   18432
#define A_VL   27648
#define ATT_DSM (2 * A_STG)

__global__ __launch_bounds__(256, 2) void attn_kernel()
{
    extern __shared__ uint8_t dyn[];
    const uint32_t sb = smem_u32(dyn);

    const int t = threadIdx.x, lane = t & 31, w = t >> 5;
    const int lr = lane >> 2, lc = lane & 3;
    const int g = lane >> 3, lr8 = lane & 7;
    const int bh = blockIdx.y, b = bh >> 4, h = bh & 15;
    const int q0 = blockIdx.x * 128;

    const __nv_bfloat16* qgh = g_qh + ((long)bh * S_ + q0) * HD_;
    const __nv_bfloat16* qgl = g_ql + ((long)bh * S_ + q0) * HD_;
    const __nv_bfloat16* khb = g_kh + (long)bh * S_ * HD_;
    const __nv_bfloat16* klb = g_kl + (long)bh * S_ * HD_;
    const __nv_bfloat16* vhb = g_vh + (long)bh * S_ * HD_;
    const __nv_bfloat16* vlb = g_vl + (long)bh * S_ * HD_;
    const float SC = 0.125f * 1.44269504088896340736f;

    // ---- stage Q [128 rows, hi/lo] across the full stage-1 buffer ----
#pragma unroll
    for (int j = 0; j < 4; j++) {
        int idx = t + j * 256, r = idx >> 3, cc = idx & 7;
        uint32_t dh = (r < 64) ? (sb + A_STG + r * 144)
                               : (sb + A_STG + A_VH + (r - 64) * 144);
        cpa16(dh + cc * 16,                     qgh + (long)r * HD_ + cc * 8);
        cpa16(dh + A_KL + cc * 16,              qgl + (long)r * HD_ + cc * 8);
    }
    cpa_commit();
    cpa_wait0();
    __syncthreads();

    uint32_t qh[4][4], ql[4][4];
    {
        uint32_t area = (w < 4) ? 0u : (uint32_t)A_VH;
        uint32_t qBH = sb + A_STG + area + ((w & 3) * 16 + lr8 + ((g & 1) << 3)) * 144 + ((g >> 1) << 4);
        uint32_t qBL = qBH + A_KL;
#pragma unroll
        for (int ks = 0; ks < 4; ks++) {
            ldsm4(qh[ks], qBH + ks * 32);
            ldsm4(ql[ks], qBL + ks * 32);
        }
    }
    __syncthreads();   // all warps done with stage-1 Q before tile-1 loads hit it

#define KV_ISSUE(stg, k0) do { \
        uint32_t base_ = sb + (stg) * A_STG; \
        _Pragma("unroll") \
        for (int j = 0; j < 2; j++) { \
            int idx = t + j * 256, r = idx >> 3, cc = idx & 7; \
            long go = (long)((k0) + r) * HD_ + cc * 8; \
            cpa16(base_ + r * 144 + cc * 16,        khb + go); \
            cpa16(base_ + A_KL + r * 144 + cc * 16, klb + go); \
            cpa16(base_ + A_VH + r * 144 + cc * 16, vhb + go); \
            cpa16(base_ + A_VL + r * 144 + cc * 16, vlb + go); \
        } \
        cpa_commit(); \
    } while (0)

    float o[8][4];
#pragma unroll
    for (int i = 0; i < 8; i++)
#pragma unroll
        for (int j = 0; j < 4; j++) o[i][j] = 0.f;
    float lacc[2] = {0.f, 0.f};

    KV_ISSUE(0, 0);

    for (int kt = 0; kt < S_ / 64; kt++) {
        const int s = kt & 1;
        const int k0 = kt * 64;

        __syncthreads();
        if (kt + 1 < S_ / 64) { KV_ISSUE(1 - s, k0 + 64); cpa_wait1(); }
        else                  { cpa_wait0(); }
        __syncthreads();

        uint32_t mw[2][2];
#pragma unroll
        for (int i = 0; i < 2; i++) {
            int q = q0 + w * 16 + lr + i * 8;
            const unsigned* mp = g_mpk + ((long)b * S_ + q) * (S_ / 32) + (k0 >> 5);
            mw[i][0] = mp[0]; mw[i][1] = mp[1];
        }

        const uint32_t stb = sb + s * A_STG;
        const uint32_t kBH = stb + (lr8 + ((g >= 2) << 3)) * 144 + ((g & 1) << 4);
        const uint32_t kBL = kBH + A_KL;
        const uint32_t vBH = stb + A_VH + (lr8 + ((g & 1) << 3)) * 144 + ((g >> 1) << 4);
        const uint32_t vBL = vBH + (A_VL - A_VH);

        float s_[8][4];
#pragma unroll
        for (int i = 0; i < 8; i++)
#pragma unroll
            for (int j = 0; j < 4; j++) s_[i][j] = 0.f;
#pragma unroll
        for (int ks = 0; ks < 4; ks++) {
#pragma unroll
            for (int np = 0; np < 4; np++) {
                uint32_t kb[4], kl4[4];
                ldsm4(kb,  kBH + np * 2304 + ks * 32);
                ldsm4(kl4, kBL + np * 2304 + ks * 32);
                mma_bf16(s_[np * 2],     qh[ks], kb);
                mma_bf16(s_[np * 2],     qh[ks], kl4);
                mma_bf16(s_[np * 2],     ql[ks], kb);
                mma_bf16(s_[np * 2 + 1], qh[ks], kb + 2);
                mma_bf16(s_[np * 2 + 1], qh[ks], kl4 + 2);
                mma_bf16(s_[np * 2 + 1], ql[ks], kb + 2);
            }
        }

#pragma unroll
        for (int i = 0; i < 2; i++) {
#pragma unroll
            for (int na = 0; na < 8; na++) {
                uint32_t wbits = mw[i][na >> 2];
                int bit = (na & 3) * 8 + lc * 2;
                float v0 = ((wbits >> bit) & 1)       ? s_[na][i * 2] * SC     : 0.f;
                float v1 = ((wbits >> (bit + 1)) & 1) ? s_[na][i * 2 + 1] * SC : 0.f;
                float p0 = ex2(v0), p1 = ex2(v1);
                s_[na][i * 2] = p0; s_[na][i * 2 + 1] = p1;
                lacc[i] += p0 + p1;
            }
        }

        uint32_t pah[4][4], pal[4][4];
#pragma unroll
        for (int ks = 0; ks < 4; ks++) {
            split_pack(s_[2 * ks][0],     s_[2 * ks][1],     pah[ks][0], pal[ks][0]);
            split_pack(s_[2 * ks][2],     s_[2 * ks][3],     pah[ks][1], pal[ks][1]);
            split_pack(s_[2 * ks + 1][0], s_[2 * ks + 1][1], pah[ks][2], pal[ks][2]);
            split_pack(s_[2 * ks + 1][2], s_[2 * ks + 1][3], pah[ks][3], pal[ks][3]);
        }

#pragma unroll
        for (int ks = 0; ks < 4; ks++) {
#pragma unroll
            for (int np = 0; np < 4; np++) {
                uint32_t vb[4], vl4[4];
                ldsm4t(vb,  vBH + ks * 2304 + np * 32);
                ldsm4t(vl4, vBL + ks * 2304 + np * 32);
                mma_bf16(o[np * 2],     pah[ks], vb);
                mma_bf16(o[np * 2],     pah[ks], vl4);
                mma_bf16(o[np * 2],     pal[ks], vb);
                mma_bf16(o[np * 2 + 1], pah[ks], vb + 2);
                mma_bf16(o[np * 2 + 1], pah[ks], vl4 + 2);
                mma_bf16(o[np * 2 + 1], pal[ks], vb + 2);
            }
        }
    }
#undef KV_ISSUE

#pragma unroll
    for (int i = 0; i < 2; i++) {
        lacc[i] += __shfl_xor_sync(0xffffffffu, lacc[i], 1);
        lacc[i] += __shfl_xor_sync(0xffffffffu, lacc[i], 2);
        float inv = 1.f / lacc[i];
        int q = q0 + w * 16 + lr + i * 8;
        __nv_bfloat16* zh = g_zh + ((long)b * S_ + q) * D_ + h * HD_;
        __nv_bfloat16* zl = g_zl + ((long)b * S_ + q) * D_ + h * HD_;
#pragma unroll
        for (int na = 0; na < 8; na++) {
            uint32_t hh, ll;
            split_pack(o[na][i * 2] * inv, o[na][i * 2 + 1] * inv, hh, ll);
            *(uint32_t*)(zh + na * 8 + lc * 2) = hh;
            *(uint32_t*)(zl + na * 8 + lc * 2) = ll;
        }
    }
}

// ---------------------------------------------------------------------------
extern "C" void kernel_launch(void* const* d_in, const int* in_sizes, int n_in,
                              void* d_out, int out_size)
{
    const float* xv   = (const float*)d_in[0];
    const float* xk   = (const float*)d_in[1];
    const float* xq   = (const float*)d_in[2];
    const int*   mask = (const int*)  d_in[3];
    const float* Wq   = (const float*)d_in[4];
    const float* bq   = (const float*)d_in[5];
    const float* Wk   = (const float*)d_in[6];
    const float* bk   = (const float*)d_in[7];
    const float* Wv   = (const float*)d_in[8];
    const float* bv   = (const float*)d_in[9];
    const float* Wo   = (const float*)d_in[10];
    const float* bo   = (const float*)d_in[11];
    float* out = (float*)d_out;

    cudaFuncSetAttribute(qkv_gemm,     cudaFuncAttributeMaxDynamicSharedMemorySize, GEMM_DSM);
    cudaFuncSetAttribute(outproj_gemm, cudaFuncAttributeMaxDynamicSharedMemorySize, GEMM_DSM);
    cudaFuncSetAttribute(attn_kernel,  cudaFuncAttributeMaxDynamicSharedMemorySize, ATT_DSM);

    split_x_kernel<<<3 * 8192, 256>>>(xq, xk, xv);
    split_w_kernel<<<4 * 1024, 256>>>(Wq, Wk, Wv, Wo);
    pack_mask_kernel<<<(B_ * S_ * (S_ / 32) + 255) / 256, 256>>>(mask);
    qkv_gemm<<<dim3(H_ / 2, 64, 3), 256, GEMM_DSM>>>(bq, bk, bv);
    attn_kernel<<<dim3(S_ / 128, B_ * H_), 256, ATT_DSM>>>();
    outproj_gemm<<<dim3(D_ / 128, (B_ * S_) / 128), 256, GEMM_DSM>>>(bo, out);
}